// round 1
// baseline (speedup 1.0000x reference)
#include <cuda_runtime.h>
#include <cuda_bf16.h>
#include <math.h>

// Problem constants
#define B_      8
#define SEQ_    1024
#define DV_     1152
#define DT_     2048
#define V_      32000
#define MROWS   (B_ * 256)        // 2048 rows after pixel shuffle
#define DSHUF   (DV_ * 4)         // 4608
#define LN_EPS  1e-5f

// Scratch (device globals: allocation-guard-safe)
__device__ float g_X[(size_t)MROWS * DSHUF];   // shuffled input  (2048 x 4608)  ~37.7MB
__device__ float g_F[(size_t)MROWS * DT_];     // features        (2048 x 2048)  ~16.8MB
__device__ float g_L[(size_t)MROWS * V_];      // logits/probs    (2048 x 32000) ~262MB

// ---------------------------------------------------------------------------
// 1) pixel shuffle gather
// ---------------------------------------------------------------------------
__global__ void shuffle_kernel(const float* __restrict__ vf, float* __restrict__ X) {
    long idx = (long)blockIdx.x * blockDim.x + threadIdx.x;
    const long total = (long)MROWS * DSHUF;
    if (idx >= total) return;
    int e  = (int)(idx % DSHUF);
    long rl = idx / DSHUF;
    int l  = (int)(rl % 256);
    int b  = (int)(rl / 256);
    int d  = e % DV_;
    int h  = 2 * (l >> 4) + (e / (2 * DV_));
    int w  = 2 * (l & 15) + ((e % (2 * DV_)) / DV_);
    X[idx] = vf[((long)b * SEQ_ + h * 32 + w) * DV_ + d];
}

// ---------------------------------------------------------------------------
// SGEMM NT: C[M,N] = A[M,K] * B[N,K]^T (+bias[n]).  A,B row-major, K-major.
// 128x128 tile, BK=16, 256 threads, 8x8 per-thread microtile.
// ---------------------------------------------------------------------------
__global__ __launch_bounds__(256)
void sgemm_nt(const float* __restrict__ A, const float* __restrict__ Bm,
              float* __restrict__ C, int M, int N, long K,
              const float* __restrict__ bias) {
    const int BM = 128, BN = 128, BK = 16;
    __shared__ float As[BK][BM];
    __shared__ float Bs[BK][BN];

    const int bm = blockIdx.y * BM;
    const int bn = blockIdx.x * BN;
    const int tid = threadIdx.x;
    const int tx = tid & 15;        // 0..15
    const int ty = tid >> 4;        // 0..15

    const int lr = tid >> 2;        // 0..63
    const int lc = (tid & 3) * 4;   // 0,4,8,12

    const float* Aptr = A + (long)bm * K;
    const float* Bptr = Bm + (long)bn * K;

    float acc[8][8] = {};

    for (long k0 = 0; k0 < K; k0 += BK) {
#pragma unroll
        for (int r = 0; r < 2; r++) {
            int row = lr + 64 * r;
            float4 v = *(const float4*)(Aptr + (long)row * K + k0 + lc);
            As[lc + 0][row] = v.x; As[lc + 1][row] = v.y;
            As[lc + 2][row] = v.z; As[lc + 3][row] = v.w;
        }
#pragma unroll
        for (int r = 0; r < 2; r++) {
            int row = lr + 64 * r;
            float4 v = *(const float4*)(Bptr + (long)row * K + k0 + lc);
            Bs[lc + 0][row] = v.x; Bs[lc + 1][row] = v.y;
            Bs[lc + 2][row] = v.z; Bs[lc + 3][row] = v.w;
        }
        __syncthreads();

#pragma unroll
        for (int k = 0; k < BK; k++) {
            float a[8], b[8];
#pragma unroll
            for (int i = 0; i < 8; i++) a[i] = As[k][ty * 8 + i];
#pragma unroll
            for (int j = 0; j < 8; j++) b[j] = Bs[k][tx * 8 + j];
#pragma unroll
            for (int i = 0; i < 8; i++)
#pragma unroll
                for (int j = 0; j < 8; j++) acc[i][j] += a[i] * b[j];
        }
        __syncthreads();
    }

#pragma unroll
    for (int i = 0; i < 8; i++) {
        int row = bm + ty * 8 + i;
#pragma unroll
        for (int j = 0; j < 8; j++) {
            int col = bn + tx * 8 + j;
            float v = acc[i][j];
            if (bias) v += bias[col];
            C[(long)row * N + col] = v;
        }
    }
}

// ---------------------------------------------------------------------------
// SGEMM NN: C[M,N] = A[M,K] * B[K,N].  A row-major (K-major), B row-major (N-major).
// ---------------------------------------------------------------------------
__global__ __launch_bounds__(256)
void sgemm_nn(const float* __restrict__ A, const float* __restrict__ Bm,
              float* __restrict__ C, int M, int N, long K) {
    const int BM = 128, BN = 128, BK = 16;
    __shared__ float As[BK][BM];
    __shared__ float Bs[BK][BN];

    const int bm = blockIdx.y * BM;
    const int bn = blockIdx.x * BN;
    const int tid = threadIdx.x;
    const int tx = tid & 15;
    const int ty = tid >> 4;

    const int lr = tid >> 2;        // 0..63 (A loads)
    const int lc = (tid & 3) * 4;   // 0,4,8,12

    const int br = tid >> 5;        // 0..7   (B loads)
    const int bc = (tid & 31) * 4;  // 0..124

    const float* Aptr = A + (long)bm * K;

    float acc[8][8] = {};

    for (long k0 = 0; k0 < K; k0 += BK) {
#pragma unroll
        for (int r = 0; r < 2; r++) {
            int row = lr + 64 * r;
            float4 v = *(const float4*)(Aptr + (long)row * K + k0 + lc);
            As[lc + 0][row] = v.x; As[lc + 1][row] = v.y;
            As[lc + 2][row] = v.z; As[lc + 3][row] = v.w;
        }
#pragma unroll
        for (int r = 0; r < 2; r++) {
            int krow = br + 8 * r;
            float4 v = *(const float4*)(Bm + (k0 + krow) * (long)N + bn + bc);
            Bs[krow][bc + 0] = v.x; Bs[krow][bc + 1] = v.y;
            Bs[krow][bc + 2] = v.z; Bs[krow][bc + 3] = v.w;
        }
        __syncthreads();

#pragma unroll
        for (int k = 0; k < BK; k++) {
            float a[8], b[8];
#pragma unroll
            for (int i = 0; i < 8; i++) a[i] = As[k][ty * 8 + i];
#pragma unroll
            for (int j = 0; j < 8; j++) b[j] = Bs[k][tx * 8 + j];
#pragma unroll
            for (int i = 0; i < 8; i++)
#pragma unroll
                for (int j = 0; j < 8; j++) acc[i][j] += a[i] * b[j];
        }
        __syncthreads();
    }

#pragma unroll
    for (int i = 0; i < 8; i++) {
        int row = bm + ty * 8 + i;
#pragma unroll
        for (int j = 0; j < 8; j++) {
            C[(long)row * N + bn + tx * 8 + j] = acc[i][j];
        }
    }
}

// ---------------------------------------------------------------------------
// Block reduction helpers
// ---------------------------------------------------------------------------
__device__ __forceinline__ float block_reduce_sum(float v) {
    __shared__ float sh[32];
    int lane = threadIdx.x & 31, wid = threadIdx.x >> 5;
#pragma unroll
    for (int o = 16; o > 0; o >>= 1) v += __shfl_xor_sync(0xffffffff, v, o);
    if (lane == 0) sh[wid] = v;
    __syncthreads();
    int nw = blockDim.x >> 5;
    v = (threadIdx.x < nw) ? sh[threadIdx.x] : 0.f;
    if (wid == 0) {
#pragma unroll
        for (int o = 16; o > 0; o >>= 1) v += __shfl_xor_sync(0xffffffff, v, o);
        if (lane == 0) sh[0] = v;
    }
    __syncthreads();
    float r = sh[0];
    __syncthreads();
    return r;
}

__device__ __forceinline__ float block_reduce_max(float v) {
    __shared__ float sh[32];
    int lane = threadIdx.x & 31, wid = threadIdx.x >> 5;
#pragma unroll
    for (int o = 16; o > 0; o >>= 1) v = fmaxf(v, __shfl_xor_sync(0xffffffff, v, o));
    if (lane == 0) sh[wid] = v;
    __syncthreads();
    int nw = blockDim.x >> 5;
    v = (threadIdx.x < nw) ? sh[threadIdx.x] : -INFINITY;
    if (wid == 0) {
#pragma unroll
        for (int o = 16; o > 0; o >>= 1) v = fmaxf(v, __shfl_xor_sync(0xffffffff, v, o));
        if (lane == 0) sh[0] = v;
    }
    __syncthreads();
    float r = sh[0];
    __syncthreads();
    return r;
}

// ---------------------------------------------------------------------------
// 3) LayerNorm over last dim (2048), in place, one block per row
// ---------------------------------------------------------------------------
__global__ void ln_kernel(float* __restrict__ F) {
    float* p = F + (long)blockIdx.x * DT_;
    float s = 0.f, ss = 0.f;
    for (int i = threadIdx.x; i < DT_; i += blockDim.x) {
        float v = p[i];
        s += v; ss += v * v;
    }
    s  = block_reduce_sum(s);
    ss = block_reduce_sum(ss);
    float mu  = s * (1.0f / DT_);
    float var = ss * (1.0f / DT_) - mu * mu;
    float rstd = rsqrtf(var + LN_EPS);
    for (int i = threadIdx.x; i < DT_; i += blockDim.x)
        p[i] = (p[i] - mu) * rstd;
}

// ---------------------------------------------------------------------------
// 5) softmax over vocab (32000), in place, one block per row
// ---------------------------------------------------------------------------
__global__ void softmax_rows(float* __restrict__ L) {
    float* p = L + (long)blockIdx.x * V_;
    float m = -INFINITY;
    for (int i = threadIdx.x; i < V_; i += blockDim.x) m = fmaxf(m, p[i]);
    m = block_reduce_max(m);
    float s = 0.f;
    for (int i = threadIdx.x; i < V_; i += blockDim.x) s += __expf(p[i] - m);
    s = block_reduce_sum(s);
    float inv = 1.0f / s;
    for (int i = threadIdx.x; i < V_; i += blockDim.x)
        p[i] = __expf(p[i] - m) * inv;
}

// ---------------------------------------------------------------------------
// Launch
// ---------------------------------------------------------------------------
extern "C" void kernel_launch(void* const* d_in, const int* in_sizes, int n_in,
                              void* d_out, int out_size) {
    const float* vf    = (const float*)d_in[0];  // vision_feats (8,1024,1152)
    const float* embed = (const float*)d_in[1];  // llm_token_embed (32000,2048)
    const float* W1w   = (const float*)d_in[2];  // (2048,4608)
    const float* W1b   = (const float*)d_in[3];  // (2048,)
    const float* W2w   = (const float*)d_in[4];  // (32000,2048)
    float* out = (float*)d_out;                  // (8,256,2048) f32

    float *X, *F, *L;
    cudaGetSymbolAddress((void**)&X, g_X);
    cudaGetSymbolAddress((void**)&F, g_F);
    cudaGetSymbolAddress((void**)&L, g_L);

    // 1) pixel shuffle
    {
        long total = (long)MROWS * DSHUF;
        int blocks = (int)((total + 255) / 256);
        shuffle_kernel<<<blocks, 256>>>(vf, X);
    }
    // 2) F = X @ W1^T + b   (2048 x 2048, K=4608)
    sgemm_nt<<<dim3(DT_ / 128, MROWS / 128), 256>>>(X, W1w, F, MROWS, DT_, DSHUF, W1b);
    // 3) LayerNorm in place
    ln_kernel<<<MROWS, 256>>>(F);
    // 4) L = F @ W2^T       (2048 x 32000, K=2048)
    sgemm_nt<<<dim3(V_ / 128, MROWS / 128), 256>>>(F, W2w, L, MROWS, V_, DT_, nullptr);
    // 5) softmax rows in place
    softmax_rows<<<MROWS, 256>>>(L);
    // 6) out = P @ E        (2048 x 2048, K=32000)
    sgemm_nn<<<dim3(DT_ / 128, MROWS / 128), 256>>>(L, embed, out, MROWS, DT_, V_);
}

// round 3
// speedup vs baseline: 3.1398x; 3.1398x over previous
#include <cuda_runtime.h>
#include <cstdint>
#include <math.h>

// Problem constants
#define B_      8
#define SEQ_    1024
#define DV_     1152
#define DT_     2048
#define V_      32000
#define MROWS   2048              // B*256 rows after pixel shuffle
#define DSHUF   4608              // DV*4
#define LN_EPS  1e-5f

// GEMM tiling
#define BM      128
#define BN      128
#define BKK     32
#define STAGES  4
#define PA      36                // A smem pitch (floats): banks (4q+c) conflict-free
#define PBNN    136               // NN B smem pitch (floats): banks (8k+n) conflict-free
#define ASZ     (BM * PA)                 // 4608 floats
#define BSZ_NT  (BN * PA)                 // 4608 floats
#define BSZ_NN  (BKK * PBNN)              // 4352 floats

// Scratch (device globals: allocation-guard-safe)
__device__ float g_X  [(size_t)MROWS * DSHUF];   // shuffled input, tf32-rounded
__device__ float g_F  [(size_t)MROWS * DT_];     // features
__device__ float g_L  [(size_t)MROWS * V_];      // logits / probs
__device__ float g_W1r[(size_t)DT_   * DSHUF];   // W1 tf32-rounded
__device__ float g_W2r[(size_t)V_    * DT_];     // W2 tf32-rounded
__device__ float g_Er [(size_t)V_    * DT_];     // embed tf32-rounded

// ---------------------------------------------------------------------------
// helpers
// ---------------------------------------------------------------------------
__device__ __forceinline__ uint32_t smem_u32(const void* p) {
    uint32_t a;
    asm("{ .reg .u64 t; cvta.to.shared.u64 t, %1; cvt.u32.u64 %0, t; }" : "=r"(a) : "l"(p));
    return a;
}
__device__ __forceinline__ float tf32r(float x) {
    uint32_t u;
    asm("cvt.rna.tf32.f32 %0, %1;" : "=r"(u) : "f"(x));
    return __uint_as_float(u);
}

#define CP_ASYNC16(dst, src) \
    asm volatile("cp.async.cg.shared.global [%0], [%1], 16;" :: "r"(dst), "l"(src))
#define CP_COMMIT()  asm volatile("cp.async.commit_group;")
#define CP_WAIT(n)   asm volatile("cp.async.wait_group %0;" :: "n"(n))

__device__ __forceinline__ void mma_tf32(float* d, const uint32_t* a, const uint32_t* b) {
    asm volatile(
        "mma.sync.aligned.m16n8k8.row.col.f32.tf32.tf32.f32 "
        "{%0,%1,%2,%3}, {%4,%5,%6,%7}, {%8,%9}, {%0,%1,%2,%3};"
        : "+f"(d[0]), "+f"(d[1]), "+f"(d[2]), "+f"(d[3])
        : "r"(a[0]), "r"(a[1]), "r"(a[2]), "r"(a[3]), "r"(b[0]), "r"(b[1]));
}

// ---------------------------------------------------------------------------
// tf32 tensor-core GEMM via mma.sync.
//   NT=true : C[M,N] = A[M,K] * B[N,K]^T    (A,B K-major)
//   NT=false: C[M,N] = A[M,K] * B[K,N]      (B N-major)
// 256 threads, 128x128 tile, BK=32, 4-stage cp.async pipeline.
// All operands must be pre-rounded to tf32 (mma truncation then exact).
// ---------------------------------------------------------------------------
template<bool NT>
__global__ __launch_bounds__(256, 1)
void gemm_mma(const float* __restrict__ A, const float* __restrict__ Bg,
              float* __restrict__ C, int M, int N, int K) {
    extern __shared__ __align__(128) float sm[];
    const uint32_t sbase = smem_u32(sm);

    const int tid  = threadIdx.x;
    const int warp = tid >> 5;
    const int lane = tid & 31;
    const int gq   = lane >> 2;      // group id
    const int tg   = lane & 3;       // thread in group
    const int wm   = (warp & 1) * 64;
    const int wn   = (warp >> 1) * 32;

    const int bm = blockIdx.x * BM;
    const int bn = blockIdx.y * BN;

    constexpr int BSZ = NT ? BSZ_NT : BSZ_NN;
    constexpr int STG = ASZ + BSZ;               // floats per stage

    const int NK = K / BKK;

    // ---- stage loader ----
    auto load_stage = [&](int f) {
        const int slot = f & (STAGES - 1);
        const uint32_t sA = sbase + (uint32_t)(slot * STG) * 4u;
        const uint32_t sB = sA + ASZ * 4u;
        const float* Ag = A + (size_t)bm * K + (size_t)f * BKK;
#pragma unroll
        for (int t = 0; t < 4; t++) {            // A: 128 rows x 32 floats
            int id = tid + t * 256;
            int row = id >> 3, c4 = id & 7;
            CP_ASYNC16(sA + (uint32_t)(row * PA + c4 * 4) * 4u,
                       Ag + (size_t)row * K + c4 * 4);
        }
        if (NT) {
            const float* Bp = Bg + (size_t)bn * K + (size_t)f * BKK;
#pragma unroll
            for (int t = 0; t < 4; t++) {        // B: 128 rows x 32 floats
                int id = tid + t * 256;
                int row = id >> 3, c4 = id & 7;
                CP_ASYNC16(sB + (uint32_t)(row * PA + c4 * 4) * 4u,
                           Bp + (size_t)row * K + c4 * 4);
            }
        } else {
            const float* Bp = Bg + (size_t)f * BKK * N + bn;
#pragma unroll
            for (int t = 0; t < 4; t++) {        // B: 32 rows x 128 floats
                int id = tid + t * 256;
                int row = id >> 5, c4 = id & 31;
                CP_ASYNC16(sB + (uint32_t)(row * PBNN + c4 * 4) * 4u,
                           Bp + (size_t)row * N + c4 * 4);
            }
        }
    };

    float acc[4][4][4];
#pragma unroll
    for (int i = 0; i < 4; i++)
#pragma unroll
        for (int j = 0; j < 4; j++)
#pragma unroll
            for (int r = 0; r < 4; r++) acc[i][j][r] = 0.f;

#pragma unroll
    for (int f = 0; f < STAGES - 1; f++) { load_stage(f); CP_COMMIT(); }

    for (int i = 0; i < NK; i++) {
        CP_WAIT(STAGES - 2);
        __syncthreads();

        const int slot = i & (STAGES - 1);
        const float* As = sm + slot * STG;
        const float* Bs = As + ASZ;

#pragma unroll
        for (int ks = 0; ks < 4; ks++) {
            uint32_t a[4][4];
#pragma unroll
            for (int mi = 0; mi < 4; mi++) {
                int r = wm + mi * 16 + gq;
                int c = ks * 8 + tg;
                a[mi][0] = __float_as_uint(As[r * PA + c]);
                a[mi][1] = __float_as_uint(As[(r + 8) * PA + c]);
                a[mi][2] = __float_as_uint(As[r * PA + c + 4]);
                a[mi][3] = __float_as_uint(As[(r + 8) * PA + c + 4]);
            }
            uint32_t b[4][2];
#pragma unroll
            for (int ni = 0; ni < 4; ni++) {
                if (NT) {
                    int n = wn + ni * 8 + gq;
                    int c = ks * 8 + tg;
                    b[ni][0] = __float_as_uint(Bs[n * PA + c]);
                    b[ni][1] = __float_as_uint(Bs[n * PA + c + 4]);
                } else {
                    int n = wn + ni * 8 + gq;
                    b[ni][0] = __float_as_uint(Bs[(ks * 8 + tg) * PBNN + n]);
                    b[ni][1] = __float_as_uint(Bs[(ks * 8 + tg + 4) * PBNN + n]);
                }
            }
#pragma unroll
            for (int mi = 0; mi < 4; mi++)
#pragma unroll
                for (int ni = 0; ni < 4; ni++)
                    mma_tf32(acc[mi][ni], a[mi], b[ni]);
        }
        __syncthreads();

        const int f = i + STAGES - 1;
        if (f < NK) load_stage(f);
        CP_COMMIT();                 // unconditional: keeps group FIFO stable
    }

    // ---- epilogue: direct float2 stores ----
#pragma unroll
    for (int mi = 0; mi < 4; mi++) {
#pragma unroll
        for (int ni = 0; ni < 4; ni++) {
            int r0 = bm + wm + mi * 16 + gq;
            int c0 = bn + wn + ni * 8 + tg * 2;
            float2 v0 = make_float2(acc[mi][ni][0], acc[mi][ni][1]);
            float2 v1 = make_float2(acc[mi][ni][2], acc[mi][ni][3]);
            *(float2*)(C + (size_t)r0 * N + c0)       = v0;
            *(float2*)(C + (size_t)(r0 + 8) * N + c0) = v1;
        }
    }
}

// ---------------------------------------------------------------------------
// pixel shuffle gather (+ tf32 round)
// ---------------------------------------------------------------------------
__global__ void shuffle_kernel(const float* __restrict__ vf, float* __restrict__ X) {
    long idx = (long)blockIdx.x * blockDim.x + threadIdx.x;
    const long total = (long)MROWS * DSHUF;
    if (idx >= total) return;
    int e  = (int)(idx % DSHUF);
    long rl = idx / DSHUF;
    int l  = (int)(rl % 256);
    int b  = (int)(rl / 256);
    int d  = e % DV_;
    int h  = 2 * (l >> 4) + (e / (2 * DV_));
    int w  = 2 * (l & 15) + ((e % (2 * DV_)) / DV_);
    X[idx] = tf32r(vf[((long)b * SEQ_ + h * 32 + w) * DV_ + d]);
}

// ---------------------------------------------------------------------------
// tf32-rounding copy (float4 vectorized)
// ---------------------------------------------------------------------------
__global__ void round_copy(const float4* __restrict__ in, float4* __restrict__ out, long n4) {
    long i = (long)blockIdx.x * blockDim.x + threadIdx.x;
    if (i >= n4) return;
    float4 v = in[i];
    v.x = tf32r(v.x); v.y = tf32r(v.y); v.z = tf32r(v.z); v.w = tf32r(v.w);
    out[i] = v;
}

// ---------------------------------------------------------------------------
// Block reductions
// ---------------------------------------------------------------------------
__device__ __forceinline__ float block_reduce_sum(float v) {
    __shared__ float sh[32];
    int lane = threadIdx.x & 31, wid = threadIdx.x >> 5;
#pragma unroll
    for (int o = 16; o > 0; o >>= 1) v += __shfl_xor_sync(0xffffffff, v, o);
    if (lane == 0) sh[wid] = v;
    __syncthreads();
    int nw = blockDim.x >> 5;
    v = (threadIdx.x < nw) ? sh[threadIdx.x] : 0.f;
    if (wid == 0) {
#pragma unroll
        for (int o = 16; o > 0; o >>= 1) v += __shfl_xor_sync(0xffffffff, v, o);
        if (lane == 0) sh[0] = v;
    }
    __syncthreads();
    float r = sh[0];
    __syncthreads();
    return r;
}
__device__ __forceinline__ float block_reduce_max(float v) {
    __shared__ float sh[32];
    int lane = threadIdx.x & 31, wid = threadIdx.x >> 5;
#pragma unroll
    for (int o = 16; o > 0; o >>= 1) v = fmaxf(v, __shfl_xor_sync(0xffffffff, v, o));
    if (lane == 0) sh[wid] = v;
    __syncthreads();
    int nw = blockDim.x >> 5;
    v = (threadIdx.x < nw) ? sh[threadIdx.x] : -INFINITY;
    if (wid == 0) {
#pragma unroll
        for (int o = 16; o > 0; o >>= 1) v = fmaxf(v, __shfl_xor_sync(0xffffffff, v, o));
        if (lane == 0) sh[0] = v;
    }
    __syncthreads();
    float r = sh[0];
    __syncthreads();
    return r;
}

// ---------------------------------------------------------------------------
// bias + LayerNorm in place, tf32-rounded output
// ---------------------------------------------------------------------------
__global__ void ln_kernel(float* __restrict__ F, const float* __restrict__ bias) {
    float* p = F + (size_t)blockIdx.x * DT_;
    float s = 0.f, ss = 0.f;
    for (int i = threadIdx.x; i < DT_; i += blockDim.x) {
        float v = p[i] + bias[i];
        s += v; ss += v * v;
    }
    s  = block_reduce_sum(s);
    ss = block_reduce_sum(ss);
    float mu  = s * (1.0f / DT_);
    float var = ss * (1.0f / DT_) - mu * mu;
    float rstd = rsqrtf(var + LN_EPS);
    for (int i = threadIdx.x; i < DT_; i += blockDim.x)
        p[i] = tf32r((p[i] + bias[i] - mu) * rstd);
}

// ---------------------------------------------------------------------------
// softmax over vocab in place, tf32-rounded probs
// ---------------------------------------------------------------------------
__global__ void softmax_rows(float* __restrict__ L) {
    float* p = L + (size_t)blockIdx.x * V_;
    float m = -INFINITY;
    for (int i = threadIdx.x; i < V_; i += blockDim.x) m = fmaxf(m, p[i]);
    m = block_reduce_max(m);
    float s = 0.f;
    for (int i = threadIdx.x; i < V_; i += blockDim.x) s += __expf(p[i] - m);
    s = block_reduce_sum(s);
    float inv = 1.0f / s;
    for (int i = threadIdx.x; i < V_; i += blockDim.x)
        p[i] = tf32r(__expf(p[i] - m) * inv);
}

// ---------------------------------------------------------------------------
// Launch
// ---------------------------------------------------------------------------
extern "C" void kernel_launch(void* const* d_in, const int* in_sizes, int n_in,
                              void* d_out, int out_size) {
    const float* vf    = (const float*)d_in[0];  // vision_feats (8,1024,1152)
    const float* embed = (const float*)d_in[1];  // llm_token_embed (32000,2048)
    const float* W1w   = (const float*)d_in[2];  // (2048,4608)
    const float* W1b   = (const float*)d_in[3];  // (2048,)
    const float* W2w   = (const float*)d_in[4];  // (32000,2048)
    float* out = (float*)d_out;                  // (8,256,2048) f32

    float *X, *F, *L, *W1r, *W2r, *Er;
    cudaGetSymbolAddress((void**)&X,   g_X);
    cudaGetSymbolAddress((void**)&F,   g_F);
    cudaGetSymbolAddress((void**)&L,   g_L);
    cudaGetSymbolAddress((void**)&W1r, g_W1r);
    cudaGetSymbolAddress((void**)&W2r, g_W2r);
    cudaGetSymbolAddress((void**)&Er,  g_Er);

    const int SMEM_NT = STAGES * (ASZ + BSZ_NT) * 4;   // 147456
    const int SMEM_NN = STAGES * (ASZ + BSZ_NN) * 4;   // 143360
    cudaFuncSetAttribute(gemm_mma<true>,  cudaFuncAttributeMaxDynamicSharedMemorySize, SMEM_NT);
    cudaFuncSetAttribute(gemm_mma<false>, cudaFuncAttributeMaxDynamicSharedMemorySize, SMEM_NN);

    // 1) pixel shuffle (tf32-rounded)
    {
        long total = (long)MROWS * DSHUF;
        shuffle_kernel<<<(int)((total + 255) / 256), 256>>>(vf, X);
    }
    // tf32-rounded operand copies
    {
        long n;
        n = (long)DT_ * DSHUF / 4;
        round_copy<<<(int)((n + 255) / 256), 256>>>((const float4*)W1w, (float4*)W1r, n);
        n = (long)V_ * DT_ / 4;
        round_copy<<<(int)((n + 255) / 256), 256>>>((const float4*)W2w, (float4*)W2r, n);
        round_copy<<<(int)((n + 255) / 256), 256>>>((const float4*)embed, (float4*)Er, n);
    }
    // 2) F = X @ W1^T        (2048 x 2048, K=4608)
    gemm_mma<true><<<dim3(MROWS / BM, DT_ / BN), 256, SMEM_NT>>>(X, W1r, F, MROWS, DT_, DSHUF);
    // 3) bias + LayerNorm
    ln_kernel<<<MROWS, 256>>>(F, W1b);
    // 4) L = F @ W2^T        (2048 x 32000, K=2048)
    gemm_mma<true><<<dim3(MROWS / BM, V_ / BN), 256, SMEM_NT>>>(F, W2r, L, MROWS, V_, DT_);
    // 5) softmax rows
    softmax_rows<<<MROWS, 256>>>(L);
    // 6) out = P @ Er        (2048 x 2048, K=32000, NN)
    gemm_mma<false><<<dim3(MROWS / BM, DT_ / BN), 256, SMEM_NN>>>(L, Er, out, MROWS, DT_, V_);
}

// round 4
// speedup vs baseline: 6.7905x; 2.1627x over previous
#include <cuda_runtime.h>
#include <cuda_fp16.h>
#include <cstdint>
#include <math.h>

// Problem constants
#define B_      8
#define SEQ_    1024
#define DV_     1152
#define DT_     2048
#define V_      32000
#define MROWS   2048
#define DSHUF   4608
#define LN_EPS  1e-5f

// GEMM tiling (fp16 operands)
#define BM      256
#define BN      128
#define BKH     64                 // K elems per stage (= 128 bytes)
#define STAGES  3
#define NTH     512
#define ASTG    (BM * 128)         // bytes per A stage
#define BSTG    (BN * 128)
#define STGB    (ASTG + BSTG)      // 49152
#define SMEM_DYN (STAGES * STGB)   // 147456

// Scratch (device globals: allocation-guard-safe)
__device__ __half g_Xh [(size_t)MROWS * DSHUF];
__device__ __half g_W1h[(size_t)DT_   * DSHUF];
__device__ float  g_F  [(size_t)MROWS * DT_];
__device__ __half g_Fh [(size_t)MROWS * DT_];
__device__ __half g_W2h[(size_t)V_    * DT_];
__device__ __half g_Ph [(size_t)MROWS * V_];     // exp(logits), half
__device__ __half g_ETh[(size_t)DT_   * V_];     // embed^T, half
__device__ float  g_Zinv[MROWS];

// ---------------------------------------------------------------------------
// helpers
// ---------------------------------------------------------------------------
__device__ __forceinline__ uint32_t smem_u32(const void* p) {
    uint32_t a;
    asm("{ .reg .u64 t; cvta.to.shared.u64 t, %1; cvt.u32.u64 %0, t; }" : "=r"(a) : "l"(p));
    return a;
}
#define CP16(d, s) \
    asm volatile("cp.async.cg.shared.global [%0], [%1], 16;" :: "r"(d), "l"(s))
#define CP_COMMIT()  asm volatile("cp.async.commit_group;")
#define CP_WAIT(n)   asm volatile("cp.async.wait_group %0;" :: "n"(n))

__device__ __forceinline__ void ldsm4(uint32_t& r0, uint32_t& r1, uint32_t& r2,
                                      uint32_t& r3, uint32_t a) {
    asm volatile("ldmatrix.sync.aligned.m8n8.x4.shared.b16 {%0,%1,%2,%3}, [%4];"
                 : "=r"(r0), "=r"(r1), "=r"(r2), "=r"(r3) : "r"(a));
}
__device__ __forceinline__ void mma_f16(float* d, const uint32_t* a,
                                        uint32_t b0, uint32_t b1) {
    asm volatile(
        "mma.sync.aligned.m16n8k16.row.col.f32.f16.f16.f32 "
        "{%0,%1,%2,%3}, {%4,%5,%6,%7}, {%8,%9}, {%0,%1,%2,%3};"
        : "+f"(d[0]), "+f"(d[1]), "+f"(d[2]), "+f"(d[3])
        : "r"(a[0]), "r"(a[1]), "r"(a[2]), "r"(a[3]), "r"(b0), "r"(b1));
}

// ---------------------------------------------------------------------------
// fp16 NT GEMM: C[M,N] = A[M,K] * B[N,K]^T, f32 accumulate.
// 512 threads, 256x128 tile, BK=64, 3-stage cp.async, ldmatrix fragments.
// MODE: 0 = plain f32 store; 1 = half(exp(acc)) store; 2 = f32 * scale[row].
// ---------------------------------------------------------------------------
template<int MODE>
__global__ __launch_bounds__(NTH, 1)
void gemm_h(const __half* __restrict__ A, const __half* __restrict__ Bw,
            void* __restrict__ Cv, const float* __restrict__ scale,
            int M, int N, int K)
{
    extern __shared__ __align__(128) char sm[];
    const uint32_t sb = smem_u32(sm);
    const int tid  = threadIdx.x;
    const int warp = tid >> 5;
    const int lane = tid & 31;
    const int gq   = lane >> 2;
    const int tg   = lane & 3;
    const int wm   = (warp & 3) * 64;
    const int wn   = (warp >> 2) * 32;
    const int bm   = blockIdx.x * BM;
    const int bn   = blockIdx.y * BN;
    const int NK   = K / BKH;
    const int rl   = lane & 15;    // ldmatrix row-in-tile
    const int kh   = lane >> 4;    // ldmatrix k-half

    auto load_stage = [&](int f, int slot) {
        const uint32_t sA = sb + (uint32_t)slot * STGB;
        const uint32_t sB = sA + ASTG;
        const __half* Ag = A + (size_t)bm * K + (size_t)f * BKH;
        const __half* Bg = Bw + (size_t)bn * K + (size_t)f * BKH;
#pragma unroll
        for (int t = 0; t < 4; t++) {            // A: 256 rows x 8 chunks
            int c = tid + t * NTH;
            int row = c >> 3, g = c & 7;
            CP16(sA + row * 128 + ((g ^ (row & 7)) << 4),
                 Ag + (size_t)row * K + g * 8);
        }
#pragma unroll
        for (int t = 0; t < 2; t++) {            // B: 128 rows x 8 chunks
            int c = tid + t * NTH;
            int row = c >> 3, g = c & 7;
            CP16(sB + row * 128 + ((g ^ (row & 7)) << 4),
                 Bg + (size_t)row * K + g * 8);
        }
    };

    float acc[4][4][4];
#pragma unroll
    for (int i = 0; i < 4; i++)
#pragma unroll
        for (int j = 0; j < 4; j++)
#pragma unroll
            for (int r = 0; r < 4; r++) acc[i][j][r] = 0.f;

    load_stage(0, 0); CP_COMMIT();
    load_stage(1, 1); CP_COMMIT();

    int slot = 0;
    for (int i = 0; i < NK; i++) {
        CP_WAIT(1);
        __syncthreads();

        const uint32_t sA = sb + (uint32_t)slot * STGB;
        const uint32_t sB = sA + ASTG;

#pragma unroll
        for (int ks = 0; ks < 4; ks++) {
            const int g = ks * 2 + kh;
            uint32_t a[4][4];
#pragma unroll
            for (int mi = 0; mi < 4; mi++) {
                int row = wm + mi * 16 + rl;
                ldsm4(a[mi][0], a[mi][1], a[mi][2], a[mi][3],
                      sA + row * 128 + ((g ^ (row & 7)) << 4));
            }
            uint32_t bf[2][4];
#pragma unroll
            for (int n2 = 0; n2 < 2; n2++) {
                int row = wn + n2 * 16 + rl;
                ldsm4(bf[n2][0], bf[n2][1], bf[n2][2], bf[n2][3],
                      sB + row * 128 + ((g ^ (row & 7)) << 4));
            }
#pragma unroll
            for (int mi = 0; mi < 4; mi++)
#pragma unroll
                for (int ni = 0; ni < 4; ni++)
                    mma_f16(acc[mi][ni], a[mi],
                            bf[ni >> 1][ni & 1], bf[ni >> 1][(ni & 1) + 2]);
        }
        __syncthreads();

        const int f = i + STAGES - 1;
        if (f < NK) {
            int ws = slot + STAGES - 1; if (ws >= STAGES) ws -= STAGES;
            load_stage(f, ws);
        }
        CP_COMMIT();                 // unconditional: stable group FIFO
        if (++slot == STAGES) slot = 0;
    }

    // ---- epilogue ----
#pragma unroll
    for (int mi = 0; mi < 4; mi++) {
        const int r0 = bm + wm + mi * 16 + gq;
#pragma unroll
        for (int ni = 0; ni < 4; ni++) {
            const int c0 = bn + wn + ni * 8 + tg * 2;
            const float* ap = acc[mi][ni];
            if (MODE == 0) {
                float* C = (float*)Cv;
                *(float2*)(C + (size_t)r0 * N + c0)       = make_float2(ap[0], ap[1]);
                *(float2*)(C + (size_t)(r0 + 8) * N + c0) = make_float2(ap[2], ap[3]);
            } else if (MODE == 1) {
                __half2* C = (__half2*)Cv;
                C[((size_t)r0 * N + c0) >> 1] =
                    __floats2half2_rn(__expf(ap[0]), __expf(ap[1]));
                C[((size_t)(r0 + 8) * N + c0) >> 1] =
                    __floats2half2_rn(__expf(ap[2]), __expf(ap[3]));
            } else {
                const float s0 = scale[r0], s1 = scale[r0 + 8];
                float* C = (float*)Cv;
                *(float2*)(C + (size_t)r0 * N + c0)       = make_float2(ap[0] * s0, ap[1] * s0);
                *(float2*)(C + (size_t)(r0 + 8) * N + c0) = make_float2(ap[2] * s1, ap[3] * s1);
            }
        }
    }
}

// ---------------------------------------------------------------------------
// pixel shuffle gather -> half
// ---------------------------------------------------------------------------
__global__ void shuffle_kernel(const float* __restrict__ vf, __half* __restrict__ X) {
    long idx = (long)blockIdx.x * blockDim.x + threadIdx.x;
    const long total = (long)MROWS * DSHUF;
    if (idx >= total) return;
    int e  = (int)(idx % DSHUF);
    long rl = idx / DSHUF;
    int l  = (int)(rl % 256);
    int b  = (int)(rl / 256);
    int d  = e % DV_;
    int h  = 2 * (l >> 4) + (e / (2 * DV_));
    int w  = 2 * (l & 15) + ((e % (2 * DV_)) / DV_);
    X[idx] = __float2half_rn(vf[((long)b * SEQ_ + h * 32 + w) * DV_ + d]);
}

// ---------------------------------------------------------------------------
// f32 -> half convert copy (float4 -> 4 halves)
// ---------------------------------------------------------------------------
__global__ void cvt_half(const float4* __restrict__ in, __half2* __restrict__ out, long n4) {
    long i = (long)blockIdx.x * blockDim.x + threadIdx.x;
    if (i >= n4) return;
    float4 v = in[i];
    out[2 * i]     = __floats2half2_rn(v.x, v.y);
    out[2 * i + 1] = __floats2half2_rn(v.z, v.w);
}

// ---------------------------------------------------------------------------
// embed transpose: E[32000,2048] f32 -> ETh[2048,32000] half
// ---------------------------------------------------------------------------
__global__ void transpose_kernel(const float* __restrict__ in, __half* __restrict__ out) {
    __shared__ float t[32][33];
    int x = blockIdx.x * 32 + threadIdx.x;   // DT
    int y = blockIdx.y * 32 + threadIdx.y;   // V
    t[threadIdx.y][threadIdx.x] = in[(size_t)y * DT_ + x];
    __syncthreads();
    int ox = blockIdx.y * 32 + threadIdx.x;  // V
    int oy = blockIdx.x * 32 + threadIdx.y;  // DT
    out[(size_t)oy * V_ + ox] = __float2half_rn(t[threadIdx.x][threadIdx.y]);
}

// ---------------------------------------------------------------------------
// block reduce
// ---------------------------------------------------------------------------
__device__ __forceinline__ float block_reduce_sum(float v) {
    __shared__ float sh[32];
    int lane = threadIdx.x & 31, wid = threadIdx.x >> 5;
#pragma unroll
    for (int o = 16; o > 0; o >>= 1) v += __shfl_xor_sync(0xffffffff, v, o);
    if (lane == 0) sh[wid] = v;
    __syncthreads();
    int nw = blockDim.x >> 5;
    v = (threadIdx.x < nw) ? sh[threadIdx.x] : 0.f;
    if (wid == 0) {
#pragma unroll
        for (int o = 16; o > 0; o >>= 1) v += __shfl_xor_sync(0xffffffff, v, o);
        if (lane == 0) sh[0] = v;
    }
    __syncthreads();
    float r = sh[0];
    __syncthreads();
    return r;
}

// ---------------------------------------------------------------------------
// bias + LayerNorm: F(f32) -> Fh(half)
// ---------------------------------------------------------------------------
__global__ void ln_kernel(const float* __restrict__ F, const float* __restrict__ bias,
                          __half* __restrict__ Fh) {
    const float* p = F + (size_t)blockIdx.x * DT_;
    __half* o = Fh + (size_t)blockIdx.x * DT_;
    float s = 0.f, ss = 0.f;
    for (int i = threadIdx.x; i < DT_; i += blockDim.x) {
        float v = p[i] + bias[i];
        s += v; ss += v * v;
    }
    s  = block_reduce_sum(s);
    ss = block_reduce_sum(ss);
    float mu  = s * (1.0f / DT_);
    float var = ss * (1.0f / DT_) - mu * mu;
    float rstd = rsqrtf(var + LN_EPS);
    for (int i = threadIdx.x; i < DT_; i += blockDim.x)
        o[i] = __float2half_rn((p[i] + bias[i] - mu) * rstd);
}

// ---------------------------------------------------------------------------
// row sums of exp(probs-unnormalized): Zinv[r] = 1 / sum(Ph[r,:])
// ---------------------------------------------------------------------------
__global__ void rowsum_kernel(const __half2* __restrict__ Ph, float* __restrict__ Zinv) {
    const __half2* p = Ph + (size_t)blockIdx.x * (V_ / 2);
    float s = 0.f;
    for (int i = threadIdx.x; i < V_ / 2; i += blockDim.x) {
        float2 f = __half22float2(p[i]);
        s += f.x + f.y;
    }
    s = block_reduce_sum(s);
    if (threadIdx.x == 0) Zinv[blockIdx.x] = 1.0f / s;
}

// ---------------------------------------------------------------------------
// Launch
// ---------------------------------------------------------------------------
extern "C" void kernel_launch(void* const* d_in, const int* in_sizes, int n_in,
                              void* d_out, int out_size) {
    const float* vf    = (const float*)d_in[0];  // vision_feats
    const float* embed = (const float*)d_in[1];  // llm_token_embed (32000,2048)
    const float* W1w   = (const float*)d_in[2];  // (2048,4608)
    const float* W1b   = (const float*)d_in[3];  // (2048,)
    const float* W2w   = (const float*)d_in[4];  // (32000,2048)
    float* out = (float*)d_out;                  // (8,256,2048) f32

    __half *Xh, *W1h, *Fh, *W2h, *Ph, *ETh;
    float *F, *Zinv;
    cudaGetSymbolAddress((void**)&Xh,  g_Xh);
    cudaGetSymbolAddress((void**)&W1h, g_W1h);
    cudaGetSymbolAddress((void**)&F,   g_F);
    cudaGetSymbolAddress((void**)&Fh,  g_Fh);
    cudaGetSymbolAddress((void**)&W2h, g_W2h);
    cudaGetSymbolAddress((void**)&Ph,  g_Ph);
    cudaGetSymbolAddress((void**)&ETh, g_ETh);
    cudaGetSymbolAddress((void**)&Zinv, g_Zinv);

    cudaFuncSetAttribute(gemm_h<0>, cudaFuncAttributeMaxDynamicSharedMemorySize, SMEM_DYN);
    cudaFuncSetAttribute(gemm_h<1>, cudaFuncAttributeMaxDynamicSharedMemorySize, SMEM_DYN);
    cudaFuncSetAttribute(gemm_h<2>, cudaFuncAttributeMaxDynamicSharedMemorySize, SMEM_DYN);

    // 1) pixel shuffle -> half
    {
        long total = (long)MROWS * DSHUF;
        shuffle_kernel<<<(int)((total + 255) / 256), 256>>>(vf, Xh);
    }
    // operand converts
    {
        long n4 = (long)DT_ * DSHUF / 4;
        cvt_half<<<(int)((n4 + 255) / 256), 256>>>((const float4*)W1w, (__half2*)W1h, n4);
        n4 = (long)V_ * DT_ / 4;
        cvt_half<<<(int)((n4 + 255) / 256), 256>>>((const float4*)W2w, (__half2*)W2h, n4);
    }
    transpose_kernel<<<dim3(DT_ / 32, V_ / 32), dim3(32, 32)>>>(embed, ETh);

    // 2) F = X @ W1^T            (2048 x 2048, K=4608)
    gemm_h<0><<<dim3(MROWS / BM, DT_ / BN), NTH, SMEM_DYN>>>(Xh, W1h, F, nullptr, MROWS, DT_, DSHUF);
    // 3) bias + LN -> half
    ln_kernel<<<MROWS, 256>>>(F, W1b, Fh);
    // 4) Ph = exp(F @ W2^T)      (2048 x 32000, K=2048), half
    gemm_h<1><<<dim3(MROWS / BM, V_ / BN), NTH, SMEM_DYN>>>(Fh, W2h, Ph, nullptr, MROWS, V_, DT_);
    // 5) Zinv = 1 / rowsum(Ph)
    rowsum_kernel<<<MROWS, 512>>>((const __half2*)Ph, Zinv);
    // 6) out = (Ph @ ETh^T) * Zinv[row]   (2048 x 2048, K=32000)
    gemm_h<2><<<dim3(MROWS / BM, DT_ / BN), NTH, SMEM_DYN>>>(Ph, ETh, out, Zinv, MROWS, DT_, V_);
}

// round 6
// speedup vs baseline: 7.8132x; 1.1506x over previous
#include <cuda_runtime.h>
#include <cuda_fp16.h>
#include <cstdint>
#include <math.h>

// Problem constants
#define B_      8
#define SEQ_    1024
#define DV_     1152
#define DT_     2048
#define V_      32000
#define MROWS   2048
#define DSHUF   4608
#define LN_EPS  1e-5f

// GEMM tiling (fp16 operands)
#define BM      256
#define BN      128
#define BKH     64                 // K elems per stage
#define STAGES  3
#define NTH     512
#define ASTG    (BM * 128)         // bytes per A stage (256 rows x 128B)
#define BSTG    (BN * 128)         // NT: 128 n-rows x 128B; NN: 64 k-rows x 256B (same bytes)
#define STGB    (ASTG + BSTG)      // 49152
#define SMEM_DYN (STAGES * STGB)   // 147456

// Scratch (device globals: allocation-guard-safe)
__device__ __half g_Xh [(size_t)MROWS * DSHUF];
__device__ __half g_W1h[(size_t)DT_   * DSHUF];
__device__ float  g_F  [(size_t)MROWS * DT_];
__device__ __half g_Fh [(size_t)MROWS * DT_];
__device__ __half g_W2h[(size_t)V_    * DT_];
__device__ __half g_Eh [(size_t)V_    * DT_];    // embed as half, original [V, DT]
__device__ __half g_Ph [(size_t)MROWS * V_];     // exp(logits), half
__device__ float  g_Zinv[MROWS];

// ---------------------------------------------------------------------------
// helpers
// ---------------------------------------------------------------------------
__device__ __forceinline__ uint32_t smem_u32(const void* p) {
    uint32_t a;
    asm("{ .reg .u64 t; cvta.to.shared.u64 t, %1; cvt.u32.u64 %0, t; }" : "=r"(a) : "l"(p));
    return a;
}
#define CP16(d, s) \
    asm volatile("cp.async.cg.shared.global [%0], [%1], 16;" :: "r"(d), "l"(s))
#define CP_COMMIT()  asm volatile("cp.async.commit_group;")
#define CP_WAIT(n)   asm volatile("cp.async.wait_group %0;" :: "n"(n))

__device__ __forceinline__ void ldsm4(uint32_t& r0, uint32_t& r1, uint32_t& r2,
                                      uint32_t& r3, uint32_t a) {
    asm volatile("ldmatrix.sync.aligned.m8n8.x4.shared.b16 {%0,%1,%2,%3}, [%4];"
                 : "=r"(r0), "=r"(r1), "=r"(r2), "=r"(r3) : "r"(a));
}
__device__ __forceinline__ void ldsm4t(uint32_t& r0, uint32_t& r1, uint32_t& r2,
                                       uint32_t& r3, uint32_t a) {
    asm volatile("ldmatrix.sync.aligned.m8n8.x4.trans.shared.b16 {%0,%1,%2,%3}, [%4];"
                 : "=r"(r0), "=r"(r1), "=r"(r2), "=r"(r3) : "r"(a));
}
__device__ __forceinline__ void mma_f16(float* d, const uint32_t* a,
                                        uint32_t b0, uint32_t b1) {
    asm volatile(
        "mma.sync.aligned.m16n8k16.row.col.f32.f16.f16.f32 "
        "{%0,%1,%2,%3}, {%4,%5,%6,%7}, {%8,%9}, {%0,%1,%2,%3};"
        : "+f"(d[0]), "+f"(d[1]), "+f"(d[2]), "+f"(d[3])
        : "r"(a[0]), "r"(a[1]), "r"(a[2]), "r"(a[3]), "r"(b0), "r"(b1));
}

// ---------------------------------------------------------------------------
// fp16 GEMM, f32 accumulate. 512 threads, 256x128 tile, BK=64, 3-stage cp.async.
//   NN=false: C = A[M,K] * B[N,K]^T   (B K-major)
//   NN=true : C = A[M,K] * B[K,N]     (B N-major, ldmatrix.trans fragments)
// MODE: 0 = f32 store; 1 = half(exp(acc)); 2 = f32 * scale[row].
// ---------------------------------------------------------------------------
template<int MODE, bool NN>
__global__ __launch_bounds__(NTH, 1)
void gemm_h(const __half* __restrict__ A, const __half* __restrict__ Bw,
            void* __restrict__ Cv, const float* __restrict__ scale,
            int M, int N, int K)
{
    extern __shared__ __align__(128) char sm[];
    const uint32_t sb = smem_u32(sm);
    const int tid  = threadIdx.x;
    const int warp = tid >> 5;
    const int lane = tid & 31;
    const int gq   = lane >> 2;
    const int tg   = lane & 3;
    const int wm   = (warp & 3) * 64;
    const int wn   = (warp >> 2) * 32;
    const int bm   = blockIdx.x * BM;
    const int bn   = blockIdx.y * BN;
    const int NK   = K / BKH;
    const int rl   = lane & 15;    // ldmatrix row-in-tile
    const int kh   = lane >> 4;    // ldmatrix half-select

    auto load_stage = [&](int f, int slot) {
        const uint32_t sA = sb + (uint32_t)slot * STGB;
        const uint32_t sB = sA + ASTG;
        const __half* Ag = A + (size_t)bm * K + (size_t)f * BKH;
#pragma unroll
        for (int t = 0; t < 4; t++) {            // A: 256 rows x 8 chunks
            int c = tid + t * NTH;
            int row = c >> 3, g = c & 7;
            CP16(sA + row * 128 + ((g ^ (row & 7)) << 4),
                 Ag + (size_t)row * K + g * 8);
        }
        if (!NN) {
            const __half* Bg = Bw + (size_t)bn * K + (size_t)f * BKH;
#pragma unroll
            for (int t = 0; t < 2; t++) {        // B: 128 n-rows x 8 chunks
                int c = tid + t * NTH;
                int row = c >> 3, g = c & 7;
                CP16(sB + row * 128 + ((g ^ (row & 7)) << 4),
                     Bg + (size_t)row * K + g * 8);
            }
        } else {
            const __half* Bg = Bw + (size_t)f * BKH * N + bn;
#pragma unroll
            for (int t = 0; t < 2; t++) {        // B: 64 k-rows x 16 chunks (256B/row)
                int c = tid + t * NTH;
                int krow = c >> 4, ng = c & 15;
                CP16(sB + krow * 256 + ((ng ^ (krow & 7)) << 4),
                     Bg + (size_t)krow * N + ng * 8);
            }
        }
    };

    float acc[4][4][4];
#pragma unroll
    for (int i = 0; i < 4; i++)
#pragma unroll
        for (int j = 0; j < 4; j++)
#pragma unroll
            for (int r = 0; r < 4; r++) acc[i][j][r] = 0.f;

    load_stage(0, 0); CP_COMMIT();
    load_stage(1, 1); CP_COMMIT();

    int slot = 0;
    for (int i = 0; i < NK; i++) {
        CP_WAIT(1);
        __syncthreads();

        const uint32_t sA = sb + (uint32_t)slot * STGB;
        const uint32_t sB = sA + ASTG;

#pragma unroll
        for (int ks = 0; ks < 4; ks++) {
            uint32_t a[4][4];
            {
                const int g = ks * 2 + kh;
#pragma unroll
                for (int mi = 0; mi < 4; mi++) {
                    int row = wm + mi * 16 + rl;
                    ldsm4(a[mi][0], a[mi][1], a[mi][2], a[mi][3],
                          sA + row * 128 + ((g ^ (row & 7)) << 4));
                }
            }
            uint32_t bf[2][4];
            if (!NN) {
                const int g = ks * 2 + kh;
#pragma unroll
                for (int n2 = 0; n2 < 2; n2++) {
                    int row = wn + n2 * 16 + rl;
                    ldsm4(bf[n2][0], bf[n2][1], bf[n2][2], bf[n2][3],
                          sB + row * 128 + ((g ^ (row & 7)) << 4));
                }
#pragma unroll
                for (int mi = 0; mi < 4; mi++)
#pragma unroll
                    for (int ni = 0; ni < 4; ni++)
                        mma_f16(acc[mi][ni], a[mi],
                                bf[ni >> 1][ni & 1], bf[ni >> 1][(ni & 1) + 2]);
            } else {
                // trans load: each ldsm4t covers 16 k-rows x 16 n-cols.
                // lanes 0-15 address k-rows (ks*16+rl); kh selects the n 8-col half.
#pragma unroll
                for (int n2 = 0; n2 < 2; n2++) {
                    int krow = ks * 16 + rl;
                    int ng = ((wn + n2 * 16) >> 3) + kh;
                    ldsm4t(bf[n2][0], bf[n2][1], bf[n2][2], bf[n2][3],
                           sB + krow * 256 + ((ng ^ (krow & 7)) << 4));
                }
                // trans reg order: {n-lo/k-lo, n-lo/k-hi, n-hi/k-lo, n-hi/k-hi}
#pragma unroll
                for (int mi = 0; mi < 4; mi++)
#pragma unroll
                    for (int ni = 0; ni < 4; ni++)
                        mma_f16(acc[mi][ni], a[mi],
                                bf[ni >> 1][(ni & 1) * 2], bf[ni >> 1][(ni & 1) * 2 + 1]);
            }
        }
        __syncthreads();

        const int f = i + STAGES - 1;
        if (f < NK) {
            int ws = slot + STAGES - 1; if (ws >= STAGES) ws -= STAGES;
            load_stage(f, ws);
        }
        CP_COMMIT();                 // unconditional: stable group FIFO
        if (++slot == STAGES) slot = 0;
    }

    // ---- epilogue ----
#pragma unroll
    for (int mi = 0; mi < 4; mi++) {
        const int r0 = bm + wm + mi * 16 + gq;
#pragma unroll
        for (int ni = 0; ni < 4; ni++) {
            const int c0 = bn + wn + ni * 8 + tg * 2;
            const float* ap = acc[mi][ni];
            if (MODE == 0) {
                float* C = (float*)Cv;
                *(float2*)(C + (size_t)r0 * N + c0)       = make_float2(ap[0], ap[1]);
                *(float2*)(C + (size_t)(r0 + 8) * N + c0) = make_float2(ap[2], ap[3]);
            } else if (MODE == 1) {
                __half2* C = (__half2*)Cv;
                C[((size_t)r0 * N + c0) >> 1] =
                    __floats2half2_rn(__expf(ap[0]), __expf(ap[1]));
                C[((size_t)(r0 + 8) * N + c0) >> 1] =
                    __floats2half2_rn(__expf(ap[2]), __expf(ap[3]));
            } else {
                const float s0 = scale[r0], s1 = scale[r0 + 8];
                float* C = (float*)Cv;
                *(float2*)(C + (size_t)r0 * N + c0)       = make_float2(ap[0] * s0, ap[1] * s0);
                *(float2*)(C + (size_t)(r0 + 8) * N + c0) = make_float2(ap[2] * s1, ap[3] * s1);
            }
        }
    }
}

// ---------------------------------------------------------------------------
// pixel shuffle gather -> half (float2 -> half2)
// ---------------------------------------------------------------------------
__global__ void shuffle_kernel(const float* __restrict__ vf, __half2* __restrict__ X) {
    long i2 = (long)blockIdx.x * blockDim.x + threadIdx.x;
    const long total2 = (long)MROWS * DSHUF / 2;
    if (i2 >= total2) return;
    int e  = (int)(i2 % (DSHUF / 2)) * 2;
    long rl = i2 / (DSHUF / 2);
    int l  = (int)(rl % 256);
    int b  = (int)(rl / 256);
    int d  = e % DV_;
    int h  = 2 * (l >> 4) + (e / (2 * DV_));
    int w  = 2 * (l & 15) + ((e % (2 * DV_)) / DV_);
    float2 v = *(const float2*)(vf + ((long)b * SEQ_ + h * 32 + w) * DV_ + d);
    X[i2] = __floats2half2_rn(v.x, v.y);
}

// ---------------------------------------------------------------------------
// f32 -> half convert copy
// ---------------------------------------------------------------------------
__global__ void cvt_half(const float4* __restrict__ in, __half2* __restrict__ out, long n4) {
    long i = (long)blockIdx.x * blockDim.x + threadIdx.x;
    if (i >= n4) return;
    float4 v = in[i];
    out[2 * i]     = __floats2half2_rn(v.x, v.y);
    out[2 * i + 1] = __floats2half2_rn(v.z, v.w);
}

// ---------------------------------------------------------------------------
// block reduce
// ---------------------------------------------------------------------------
__device__ __forceinline__ float block_reduce_sum(float v) {
    __shared__ float sh[32];
    int lane = threadIdx.x & 31, wid = threadIdx.x >> 5;
#pragma unroll
    for (int o = 16; o > 0; o >>= 1) v += __shfl_xor_sync(0xffffffff, v, o);
    if (lane == 0) sh[wid] = v;
    __syncthreads();
    int nw = blockDim.x >> 5;
    v = (threadIdx.x < nw) ? sh[threadIdx.x] : 0.f;
    if (wid == 0) {
#pragma unroll
        for (int o = 16; o > 0; o >>= 1) v += __shfl_xor_sync(0xffffffff, v, o);
        if (lane == 0) sh[0] = v;
    }
    __syncthreads();
    float r = sh[0];
    __syncthreads();
    return r;
}

// ---------------------------------------------------------------------------
// bias + LayerNorm: F(f32) -> Fh(half)
// ---------------------------------------------------------------------------
__global__ void ln_kernel(const float* __restrict__ F, const float* __restrict__ bias,
                          __half* __restrict__ Fh) {
    const float* p = F + (size_t)blockIdx.x * DT_;
    __half* o = Fh + (size_t)blockIdx.x * DT_;
    float s = 0.f, ss = 0.f;
    for (int i = threadIdx.x; i < DT_; i += blockDim.x) {
        float v = p[i] + bias[i];
        s += v; ss += v * v;
    }
    s  = block_reduce_sum(s);
    ss = block_reduce_sum(ss);
    float mu  = s * (1.0f / DT_);
    float var = ss * (1.0f / DT_) - mu * mu;
    float rstd = rsqrtf(var + LN_EPS);
    for (int i = threadIdx.x; i < DT_; i += blockDim.x)
        o[i] = __float2half_rn((p[i] + bias[i] - mu) * rstd);
}

// ---------------------------------------------------------------------------
// Zinv[r] = 1 / sum(Ph[r,:])
// ---------------------------------------------------------------------------
__global__ void rowsum_kernel(const __half2* __restrict__ Ph, float* __restrict__ Zinv) {
    const __half2* p = Ph + (size_t)blockIdx.x * (V_ / 2);
    float s = 0.f;
    for (int i = threadIdx.x; i < V_ / 2; i += blockDim.x) {
        float2 f = __half22float2(p[i]);
        s += f.x + f.y;
    }
    s = block_reduce_sum(s);
    if (threadIdx.x == 0) Zinv[blockIdx.x] = 1.0f / s;
}

// ---------------------------------------------------------------------------
// Launch
// ---------------------------------------------------------------------------
extern "C" void kernel_launch(void* const* d_in, const int* in_sizes, int n_in,
                              void* d_out, int out_size) {
    const float* vf    = (const float*)d_in[0];  // vision_feats
    const float* embed = (const float*)d_in[1];  // llm_token_embed (32000,2048)
    const float* W1w   = (const float*)d_in[2];  // (2048,4608)
    const float* W1b   = (const float*)d_in[3];  // (2048,)
    const float* W2w   = (const float*)d_in[4];  // (32000,2048)
    float* out = (float*)d_out;                  // (8,256,2048) f32

    __half *Xh, *W1h, *Fh, *W2h, *Eh, *Ph;
    float *F, *Zinv;
    cudaGetSymbolAddress((void**)&Xh,   g_Xh);
    cudaGetSymbolAddress((void**)&W1h,  g_W1h);
    cudaGetSymbolAddress((void**)&F,    g_F);
    cudaGetSymbolAddress((void**)&Fh,   g_Fh);
    cudaGetSymbolAddress((void**)&W2h,  g_W2h);
    cudaGetSymbolAddress((void**)&Eh,   g_Eh);
    cudaGetSymbolAddress((void**)&Ph,   g_Ph);
    cudaGetSymbolAddress((void**)&Zinv, g_Zinv);

    cudaFuncSetAttribute(gemm_h<0,false>, cudaFuncAttributeMaxDynamicSharedMemorySize, SMEM_DYN);
    cudaFuncSetAttribute(gemm_h<1,false>, cudaFuncAttributeMaxDynamicSharedMemorySize, SMEM_DYN);
    cudaFuncSetAttribute(gemm_h<2,true>,  cudaFuncAttributeMaxDynamicSharedMemorySize, SMEM_DYN);

    // 1) pixel shuffle -> half
    {
        long total2 = (long)MROWS * DSHUF / 2;
        shuffle_kernel<<<(int)((total2 + 255) / 256), 256>>>(vf, (__half2*)Xh);
    }
    // operand converts
    {
        long n4 = (long)DT_ * DSHUF / 4;
        cvt_half<<<(int)((n4 + 255) / 256), 256>>>((const float4*)W1w, (__half2*)W1h, n4);
        n4 = (long)V_ * DT_ / 4;
        cvt_half<<<(int)((n4 + 255) / 256), 256>>>((const float4*)W2w, (__half2*)W2h, n4);
        cvt_half<<<(int)((n4 + 255) / 256), 256>>>((const float4*)embed, (__half2*)Eh, n4);
    }

    // 2) F = X @ W1^T            (2048 x 2048, K=4608)
    gemm_h<0,false><<<dim3(MROWS / BM, DT_ / BN), NTH, SMEM_DYN>>>(Xh, W1h, F, nullptr, MROWS, DT_, DSHUF);
    // 3) bias + LN -> half
    ln_kernel<<<MROWS, 256>>>(F, W1b, Fh);
    // 4) Ph = exp(F @ W2^T)      (2048 x 32000, K=2048), half
    gemm_h<1,false><<<dim3(MROWS / BM, V_ / BN), NTH, SMEM_DYN>>>(Fh, W2h, Ph, nullptr, MROWS, V_, DT_);
    // 5) Zinv = 1 / rowsum(Ph)
    rowsum_kernel<<<MROWS, 512>>>((const __half2*)Ph, Zinv);
    // 6) out = (Ph @ Eh) * Zinv[row]   (2048 x 2048, K=32000, NN direct on embed)
    gemm_h<2,true><<<dim3(MROWS / BM, DT_ / BN), NTH, SMEM_DYN>>>(Ph, Eh, out, Zinv, MROWS, DT_, V_);
}